// round 1
// baseline (speedup 1.0000x reference)
#include <cuda_runtime.h>
#include <math.h>

#define S_LEN  2048
#define HIDDIM 4096
#define NH     32
#define NKV    8
#define HD     128
#define GROUPS 4

// ---------------- scratch (allocation-free) ----------------
__device__ float g_Q[(size_t)S_LEN * HIDDIM];        // 32 MB
__device__ float g_K[(size_t)S_LEN * NKV * HD];      // 8 MB
__device__ float g_V[(size_t)S_LEN * NKV * HD];      // 8 MB
__device__ float g_O[(size_t)S_LEN * HIDDIM];        // 32 MB

// ---------------- GEMM: C[M,N] = A[M,K] @ B[N,K]^T ----------------
// 128x128 block tile, BK=8, 256 threads, 8x8 per thread.
__global__ __launch_bounds__(256, 2)
void gemm_nt(const float* __restrict__ A, const float* __restrict__ B,
             float* __restrict__ C, int M, int N, int K) {
    __shared__ float As[8][132];
    __shared__ float Bs[8][132];

    const int tid  = threadIdx.x;
    const int bm   = blockIdx.y * 128;
    const int bn   = blockIdx.x * 128;
    const int tx   = tid & 15;
    const int ty   = tid >> 4;
    const int lrow = tid >> 1;          // 0..127
    const int lcol = (tid & 1) * 4;     // 0 or 4

    const float* Ap = A + (size_t)(bm + lrow) * K + lcol;
    const float* Bp = B + (size_t)(bn + lrow) * K + lcol;

    float acc[8][8];
#pragma unroll
    for (int i = 0; i < 8; i++)
#pragma unroll
        for (int j = 0; j < 8; j++) acc[i][j] = 0.f;

    for (int k0 = 0; k0 < K; k0 += 8) {
        float4 av = *(const float4*)(Ap + k0);
        float4 bv = *(const float4*)(Bp + k0);
        __syncthreads();
        As[lcol + 0][lrow] = av.x; As[lcol + 1][lrow] = av.y;
        As[lcol + 2][lrow] = av.z; As[lcol + 3][lrow] = av.w;
        Bs[lcol + 0][lrow] = bv.x; Bs[lcol + 1][lrow] = bv.y;
        Bs[lcol + 2][lrow] = bv.z; Bs[lcol + 3][lrow] = bv.w;
        __syncthreads();
#pragma unroll
        for (int kk = 0; kk < 8; kk++) {
            float4 a0 = *(const float4*)&As[kk][ty * 8];
            float4 a1 = *(const float4*)&As[kk][ty * 8 + 4];
            float4 b0 = *(const float4*)&Bs[kk][tx * 8];
            float4 b1 = *(const float4*)&Bs[kk][tx * 8 + 4];
            float a[8] = {a0.x, a0.y, a0.z, a0.w, a1.x, a1.y, a1.z, a1.w};
            float b[8] = {b0.x, b0.y, b0.z, b0.w, b1.x, b1.y, b1.z, b1.w};
#pragma unroll
            for (int i = 0; i < 8; i++)
#pragma unroll
                for (int j = 0; j < 8; j++)
                    acc[i][j] = fmaf(a[i], b[j], acc[i][j]);
        }
    }

#pragma unroll
    for (int i = 0; i < 8; i++) {
        float* cp = C + (size_t)(bm + ty * 8 + i) * N + bn + tx * 8;
        float4 c0 = make_float4(acc[i][0], acc[i][1], acc[i][2], acc[i][3]);
        float4 c1 = make_float4(acc[i][4], acc[i][5], acc[i][6], acc[i][7]);
        *(float4*)(cp + 0) = c0;
        *(float4*)(cp + 4) = c1;
    }
}

// ---------------- RoPE (in-place on Q and K) ----------------
// emb = concat(freqs, freqs); out[d]    = x[d]*cos - x[d+64]*sin
//                             out[d+64] = x[d+64]*cos + x[d]*sin
__global__ void rope_kernel(float* __restrict__ Q, float* __restrict__ K) {
    int idx = blockIdx.x * blockDim.x + threadIdx.x;
    const int total = S_LEN * (NH + NKV) * 64;
    if (idx >= total) return;
    int d   = idx & 63;
    int t   = idx >> 6;
    int h   = t % (NH + NKV);
    int pos = t / (NH + NKV);

    // inv_freq = 10000^(-d/64) = 2^(-d * log2(10000)/64)
    float invf = exp2f((float)d * -0.20762050593046014f);
    float ang  = (float)pos * invf;      // same fp32 product structure as reference
    float sv, cv;
    sincosf(ang, &sv, &cv);

    float* base = (h < NH) ? (Q + (size_t)pos * HIDDIM + h * HD)
                           : (K + (size_t)pos * (NKV * HD) + (h - NH) * HD);
    float x1 = base[d];
    float x2 = base[d + 64];
    base[d]      = x1 * cv - x2 * sv;
    base[d + 64] = x2 * cv + x1 * sv;
}

// ---------------- Flash attention (fp32, causal, GQA) ----------------
// One block = (q-tile of 64 rows, head). 256 threads: tx=tid%16, ty=tid/16.
// S phase: thread owns S[ty*4+i][tx*4+j]; PV phase: O[ty*4+i][tx*8+j].
#define FA_SMEM_FLOATS (2 * 128 * 65 + 64 * 128 + 64 * 65)

__global__ __launch_bounds__(256)
void flash_attn(const float* __restrict__ Q, const float* __restrict__ K,
                const float* __restrict__ V, float* __restrict__ O) {
    extern __shared__ float sm[];
    float* Qt = sm;                    // [128][65]  d-major
    float* Kt = sm + 128 * 65;         // [128][65]  d-major
    float* Vs = sm + 2 * 128 * 65;     // [64][128]  key-major
    float* Ps = Vs + 64 * 128;         // [64][65]   q-major

    const int qb  = blockIdx.x;
    const int h   = blockIdx.y;
    const int kv  = h / GROUPS;
    const int tid = threadIdx.x;
    const int tx  = tid & 15;
    const int ty  = tid >> 4;

    // load Q tile (transposed to d-major)
    for (int idx = tid; idx < 64 * 32; idx += 256) {
        int r = idx >> 5, f4 = idx & 31;
        float4 v = *(const float4*)(Q + (size_t)(qb * 64 + r) * HIDDIM + h * HD + f4 * 4);
        Qt[(f4 * 4 + 0) * 65 + r] = v.x;
        Qt[(f4 * 4 + 1) * 65 + r] = v.y;
        Qt[(f4 * 4 + 2) * 65 + r] = v.z;
        Qt[(f4 * 4 + 3) * 65 + r] = v.w;
    }

    float m[4], l[4], o[4][8];
#pragma unroll
    for (int i = 0; i < 4; i++) {
        m[i] = -1e30f; l[i] = 0.f;
#pragma unroll
        for (int j = 0; j < 8; j++) o[i][j] = 0.f;
    }
    __syncthreads();

    const float scale = 0.08838834764831845f;  // 1/sqrt(128)

    for (int kt = 0; kt <= qb; kt++) {
        // load K (transposed) + V (natural) tiles
        for (int idx = tid; idx < 64 * 32; idx += 256) {
            int r = idx >> 5, f4 = idx & 31;
            const size_t roff = (size_t)(kt * 64 + r) * (NKV * HD) + kv * HD + f4 * 4;
            float4 kvv = *(const float4*)(K + roff);
            Kt[(f4 * 4 + 0) * 65 + r] = kvv.x;
            Kt[(f4 * 4 + 1) * 65 + r] = kvv.y;
            Kt[(f4 * 4 + 2) * 65 + r] = kvv.z;
            Kt[(f4 * 4 + 3) * 65 + r] = kvv.w;
            *(float4*)(Vs + r * 128 + f4 * 4) = *(const float4*)(V + roff);
        }
        __syncthreads();

        // ---- S = scale * Q @ K^T (4x4 per thread) ----
        float s[4][4];
#pragma unroll
        for (int i = 0; i < 4; i++)
#pragma unroll
            for (int j = 0; j < 4; j++) s[i][j] = 0.f;

#pragma unroll 4
        for (int d = 0; d < 128; d++) {
            float a[4], b[4];
#pragma unroll
            for (int i = 0; i < 4; i++) a[i] = Qt[d * 65 + ty * 4 + i];
#pragma unroll
            for (int j = 0; j < 4; j++) b[j] = Kt[d * 65 + tx * 4 + j];
#pragma unroll
            for (int i = 0; i < 4; i++)
#pragma unroll
                for (int j = 0; j < 4; j++)
                    s[i][j] = fmaf(a[i], b[j], s[i][j]);
        }

#pragma unroll
        for (int i = 0; i < 4; i++)
#pragma unroll
            for (int j = 0; j < 4; j++) s[i][j] *= scale;

        if (kt == qb) {  // causal mask on diagonal tile (tile-local offsets equal)
#pragma unroll
            for (int i = 0; i < 4; i++)
#pragma unroll
                for (int j = 0; j < 4; j++)
                    if (tx * 4 + j > ty * 4 + i) s[i][j] = -1e30f;
        }

        // ---- online softmax (row stats reduced across the 16 tx threads) ----
#pragma unroll
        for (int i = 0; i < 4; i++) {
            float rowmax = fmaxf(fmaxf(s[i][0], s[i][1]), fmaxf(s[i][2], s[i][3]));
#pragma unroll
            for (int off = 8; off >= 1; off >>= 1)
                rowmax = fmaxf(rowmax, __shfl_xor_sync(0xffffffffu, rowmax, off));
            float newm  = fmaxf(m[i], rowmax);
            float alpha = __expf(m[i] - newm);
            float rsum = 0.f;
#pragma unroll
            for (int j = 0; j < 4; j++) {
                float p = __expf(s[i][j] - newm);
                s[i][j] = p;
                rsum += p;
            }
#pragma unroll
            for (int off = 8; off >= 1; off >>= 1)
                rsum += __shfl_xor_sync(0xffffffffu, rsum, off);
            l[i] = l[i] * alpha + rsum;
            m[i] = newm;
#pragma unroll
            for (int j = 0; j < 8; j++) o[i][j] *= alpha;
        }

#pragma unroll
        for (int i = 0; i < 4; i++)
#pragma unroll
            for (int j = 0; j < 4; j++)
                Ps[(ty * 4 + i) * 65 + tx * 4 + j] = s[i][j];
        __syncthreads();

        // ---- O += P @ V (4 rows x 8 d-cols per thread) ----
#pragma unroll 2
        for (int k = 0; k < 64; k++) {
            float p[4];
#pragma unroll
            for (int i = 0; i < 4; i++) p[i] = Ps[(ty * 4 + i) * 65 + k];
            float4 v0 = *(const float4*)(Vs + k * 128 + tx * 8);
            float4 v1 = *(const float4*)(Vs + k * 128 + tx * 8 + 4);
#pragma unroll
            for (int i = 0; i < 4; i++) {
                o[i][0] = fmaf(p[i], v0.x, o[i][0]);
                o[i][1] = fmaf(p[i], v0.y, o[i][1]);
                o[i][2] = fmaf(p[i], v0.z, o[i][2]);
                o[i][3] = fmaf(p[i], v0.w, o[i][3]);
                o[i][4] = fmaf(p[i], v1.x, o[i][4]);
                o[i][5] = fmaf(p[i], v1.y, o[i][5]);
                o[i][6] = fmaf(p[i], v1.z, o[i][6]);
                o[i][7] = fmaf(p[i], v1.w, o[i][7]);
            }
        }
        __syncthreads();
    }

    // epilogue: normalize and write [token][h*HD+d]
#pragma unroll
    for (int i = 0; i < 4; i++) {
        float inv = 1.f / l[i];
        float* op = O + (size_t)(qb * 64 + ty * 4 + i) * HIDDIM + h * HD + tx * 8;
        float4 c0 = make_float4(o[i][0] * inv, o[i][1] * inv, o[i][2] * inv, o[i][3] * inv);
        float4 c1 = make_float4(o[i][4] * inv, o[i][5] * inv, o[i][6] * inv, o[i][7] * inv);
        *(float4*)(op + 0) = c0;
        *(float4*)(op + 4) = c1;
    }
}

// ---------------- launch ----------------
extern "C" void kernel_launch(void* const* d_in, const int* in_sizes, int n_in,
                              void* d_out, int out_size) {
    const float* H  = (const float*)d_in[0];
    const float* Wq = (const float*)d_in[1];
    const float* Wk = (const float*)d_in[2];
    const float* Wv = (const float*)d_in[3];
    const float* Wo = (const float*)d_in[4];
    float* out = (float*)d_out;

    float *qb, *kb, *vb, *ob;
    cudaGetSymbolAddress((void**)&qb, g_Q);
    cudaGetSymbolAddress((void**)&kb, g_K);
    cudaGetSymbolAddress((void**)&vb, g_V);
    cudaGetSymbolAddress((void**)&ob, g_O);

    // QKV projections
    gemm_nt<<<dim3(HIDDIM / 128, S_LEN / 128), 256>>>(H, Wq, qb, S_LEN, HIDDIM, HIDDIM);
    gemm_nt<<<dim3((NKV * HD) / 128, S_LEN / 128), 256>>>(H, Wk, kb, S_LEN, NKV * HD, HIDDIM);
    gemm_nt<<<dim3((NKV * HD) / 128, S_LEN / 128), 256>>>(H, Wv, vb, S_LEN, NKV * HD, HIDDIM);

    // RoPE on Q and K
    rope_kernel<<<(S_LEN * (NH + NKV) * 64) / 256, 256>>>(qb, kb);

    // attention
    const int fa_smem = FA_SMEM_FLOATS * (int)sizeof(float);
    cudaFuncSetAttribute(flash_attn, cudaFuncAttributeMaxDynamicSharedMemorySize, fa_smem);
    flash_attn<<<dim3(S_LEN / 64, NH), 256, fa_smem>>>(qb, kb, vb, ob);

    // output projection -> d_out
    gemm_nt<<<dim3(HIDDIM / 128, S_LEN / 128), 256>>>(ob, Wo, out, S_LEN, HIDDIM, HIDDIM);
}

// round 3
// speedup vs baseline: 1.9726x; 1.9726x over previous
#include <cuda_runtime.h>
#include <math.h>
#include <cstdint>

#define S_LEN  2048
#define HIDDIM 4096
#define NH     32
#define NKV    8
#define HD     128
#define GROUPS 4

// ---------------- scratch (allocation-free) ----------------
__device__ float g_Q[(size_t)S_LEN * HIDDIM];        // 32 MB
__device__ float g_K[(size_t)S_LEN * NKV * HD];      // 8 MB
__device__ float g_V[(size_t)S_LEN * NKV * HD];      // 8 MB
__device__ float g_O[(size_t)S_LEN * HIDDIM];        // 32 MB

// ================= tf32 mma.sync GEMM =================
// C[M,N] = A[M,K] @ B[N,K]^T.  fp32 in GMEM, tf32 (RNA) inside the MMA.
// CTA tile 128x128, 8 warps in 2x4 (warp tile 64x32), BK=16, 2 smem stages.

#define BK   16
#define LDA  20   // padded row stride (floats): conflict-free fragment LDS

__device__ __forceinline__ uint32_t f2tf(float x) {
    uint32_t y;
    asm("cvt.rna.tf32.f32 %0, %1;" : "=r"(y) : "f"(x));
    return y;
}

__device__ __forceinline__ void mma16n8k8(float c[4], const uint32_t a[4],
                                          const uint32_t b[2]) {
    asm volatile(
        "mma.sync.aligned.m16n8k8.row.col.f32.tf32.tf32.f32 "
        "{%0,%1,%2,%3}, {%4,%5,%6,%7}, {%8,%9}, {%0,%1,%2,%3};"
        : "+f"(c[0]), "+f"(c[1]), "+f"(c[2]), "+f"(c[3])
        : "r"(a[0]), "r"(a[1]), "r"(a[2]), "r"(a[3]), "r"(b[0]), "r"(b[1]));
}

__global__ __launch_bounds__(256, 2)
void gemm_mma(const float* __restrict__ A, const float* __restrict__ B,
              float* __restrict__ C, int M, int N, int K) {
    __shared__ float As[2][128 * LDA];
    __shared__ float Bs[2][128 * LDA];

    const int tid    = threadIdx.x;
    const int wid    = tid >> 5;
    const int lane   = tid & 31;
    const int grp    = lane >> 2;       // 0..7
    const int thr4   = lane & 3;        // 0..3
    const int warp_m = (wid & 1) * 64;
    const int warp_n = (wid >> 1) * 32;
    const int bm     = blockIdx.y * 128;
    const int bn     = blockIdx.x * 128;
    const int nk     = K / BK;

    const int r0 = tid >> 2;            // 0..63   (e = tid)
    const int q0 = tid & 3;
    const int r1 = (tid + 256) >> 2;    // 64..127 (e = tid+256)
    const int q1 = q0;

    float acc[4][4][4];
#pragma unroll
    for (int mt = 0; mt < 4; mt++)
#pragma unroll
        for (int nt = 0; nt < 4; nt++)
#pragma unroll
            for (int i = 0; i < 4; i++) acc[mt][nt][i] = 0.f;

    float4 ra[2], rb[2];

    auto gload = [&](int kc) {
        ra[0] = *(const float4*)(A + (size_t)(bm + r0) * K + kc * BK + q0 * 4);
        rb[0] = *(const float4*)(B + (size_t)(bn + r0) * K + kc * BK + q0 * 4);
        ra[1] = *(const float4*)(A + (size_t)(bm + r1) * K + kc * BK + q1 * 4);
        rb[1] = *(const float4*)(B + (size_t)(bn + r1) * K + kc * BK + q1 * 4);
    };
    auto sstore = [&](int s) {
#pragma unroll
        for (int i = 0; i < 2; i++) {
            int r = i ? r1 : r0;
            int q = i ? q1 : q0;
            float4 va = ra[i], vb = rb[i];
            uint32_t* pa = (uint32_t*)&As[s][r * LDA + q * 4];
            uint32_t* pb = (uint32_t*)&Bs[s][r * LDA + q * 4];
            *(uint2*)(pa)     = make_uint2(f2tf(va.x), f2tf(va.y));
            *(uint2*)(pa + 2) = make_uint2(f2tf(va.z), f2tf(va.w));
            *(uint2*)(pb)     = make_uint2(f2tf(vb.x), f2tf(vb.y));
            *(uint2*)(pb + 2) = make_uint2(f2tf(vb.z), f2tf(vb.w));
        }
    };

    gload(0);
    sstore(0);
    if (nk > 1) gload(1);

    for (int kc = 0; kc < nk; kc++) {
        __syncthreads();
        if (kc + 1 < nk) sstore((kc + 1) & 1);

        const uint32_t* sA = (const uint32_t*)As[kc & 1];
        const uint32_t* sB = (const uint32_t*)Bs[kc & 1];
#pragma unroll
        for (int k8 = 0; k8 < 2; k8++) {
            uint32_t af[4][4];
#pragma unroll
            for (int mt = 0; mt < 4; mt++) {
                int row = warp_m + mt * 16 + grp;
                int col = k8 * 8 + thr4;
                af[mt][0] = sA[row * LDA + col];
                af[mt][1] = sA[(row + 8) * LDA + col];
                af[mt][2] = sA[row * LDA + col + 4];
                af[mt][3] = sA[(row + 8) * LDA + col + 4];
            }
            uint32_t bf[4][2];
#pragma unroll
            for (int nt = 0; nt < 4; nt++) {
                int n = warp_n + nt * 8 + grp;
                int kcol = k8 * 8 + thr4;
                bf[nt][0] = sB[n * LDA + kcol];
                bf[nt][1] = sB[n * LDA + kcol + 4];
            }
#pragma unroll
            for (int mt = 0; mt < 4; mt++)
#pragma unroll
                for (int nt = 0; nt < 4; nt++)
                    mma16n8k8(acc[mt][nt], af[mt], bf[nt]);
        }
        if (kc + 2 < nk) gload(kc + 2);
    }

    // epilogue
#pragma unroll
    for (int mt = 0; mt < 4; mt++) {
        int row = bm + warp_m + mt * 16 + grp;
#pragma unroll
        for (int nt = 0; nt < 4; nt++) {
            int col = bn + warp_n + nt * 8 + thr4 * 2;
            *(float2*)(C + (size_t)row * N + col) =
                make_float2(acc[mt][nt][0], acc[mt][nt][1]);
            *(float2*)(C + (size_t)(row + 8) * N + col) =
                make_float2(acc[mt][nt][2], acc[mt][nt][3]);
        }
    }
}

// ---------------- RoPE (in-place on Q and K) ----------------
__global__ void rope_kernel(float* __restrict__ Q, float* __restrict__ K) {
    int idx = blockIdx.x * blockDim.x + threadIdx.x;
    const int total = S_LEN * (NH + NKV) * 64;
    if (idx >= total) return;
    int d   = idx & 63;
    int t   = idx >> 6;
    int h   = t % (NH + NKV);
    int pos = t / (NH + NKV);

    float invf = exp2f((float)d * -0.20762050593046014f);
    float ang  = (float)pos * invf;
    float sv, cv;
    sincosf(ang, &sv, &cv);

    float* base = (h < NH) ? (Q + (size_t)pos * HIDDIM + h * HD)
                           : (K + (size_t)pos * (NKV * HD) + (h - NH) * HD);
    float x1 = base[d];
    float x2 = base[d + 64];
    base[d]      = x1 * cv - x2 * sv;
    base[d + 64] = x2 * cv + x1 * sv;
}

// ---------------- Flash attention (fp32, causal, GQA) ----------------
#define FA_SMEM_FLOATS (2 * 128 * 65 + 64 * 128 + 64 * 65)

__global__ __launch_bounds__(256)
void flash_attn(const float* __restrict__ Q, const float* __restrict__ K,
                const float* __restrict__ V, float* __restrict__ O) {
    extern __shared__ float smf[];
    float* Qt = smf;                   // [128][65]  d-major
    float* Kt = smf + 128 * 65;        // [128][65]  d-major
    float* Vs = smf + 2 * 128 * 65;    // [64][128]  key-major
    float* Ps = Vs + 64 * 128;         // [64][65]   q-major

    const int qb  = blockIdx.x;
    const int h   = blockIdx.y;
    const int kv  = h / GROUPS;
    const int tid = threadIdx.x;
    const int tx  = tid & 15;
    const int ty  = tid >> 4;

    for (int idx = tid; idx < 64 * 32; idx += 256) {
        int r = idx >> 5, f4 = idx & 31;
        float4 v = *(const float4*)(Q + (size_t)(qb * 64 + r) * HIDDIM + h * HD + f4 * 4);
        Qt[(f4 * 4 + 0) * 65 + r] = v.x;
        Qt[(f4 * 4 + 1) * 65 + r] = v.y;
        Qt[(f4 * 4 + 2) * 65 + r] = v.z;
        Qt[(f4 * 4 + 3) * 65 + r] = v.w;
    }

    float m[4], l[4], o[4][8];
#pragma unroll
    for (int i = 0; i < 4; i++) {
        m[i] = -1e30f; l[i] = 0.f;
#pragma unroll
        for (int j = 0; j < 8; j++) o[i][j] = 0.f;
    }
    __syncthreads();

    const float scale = 0.08838834764831845f;

    for (int kt = 0; kt <= qb; kt++) {
        for (int idx = tid; idx < 64 * 32; idx += 256) {
            int r = idx >> 5, f4 = idx & 31;
            const size_t roff = (size_t)(kt * 64 + r) * (NKV * HD) + kv * HD + f4 * 4;
            float4 kvv = *(const float4*)(K + roff);
            Kt[(f4 * 4 + 0) * 65 + r] = kvv.x;
            Kt[(f4 * 4 + 1) * 65 + r] = kvv.y;
            Kt[(f4 * 4 + 2) * 65 + r] = kvv.z;
            Kt[(f4 * 4 + 3) * 65 + r] = kvv.w;
            *(float4*)(Vs + r * 128 + f4 * 4) = *(const float4*)(V + roff);
        }
        __syncthreads();

        float s[4][4];
#pragma unroll
        for (int i = 0; i < 4; i++)
#pragma unroll
            for (int j = 0; j < 4; j++) s[i][j] = 0.f;

#pragma unroll 4
        for (int d = 0; d < 128; d++) {
            float a[4], b[4];
#pragma unroll
            for (int i = 0; i < 4; i++) a[i] = Qt[d * 65 + ty * 4 + i];
#pragma unroll
            for (int j = 0; j < 4; j++) b[j] = Kt[d * 65 + tx * 4 + j];
#pragma unroll
            for (int i = 0; i < 4; i++)
#pragma unroll
                for (int j = 0; j < 4; j++)
                    s[i][j] = fmaf(a[i], b[j], s[i][j]);
        }

#pragma unroll
        for (int i = 0; i < 4; i++)
#pragma unroll
            for (int j = 0; j < 4; j++) s[i][j] *= scale;

        if (kt == qb) {
#pragma unroll
            for (int i = 0; i < 4; i++)
#pragma unroll
                for (int j = 0; j < 4; j++)
                    if (tx * 4 + j > ty * 4 + i) s[i][j] = -1e30f;
        }

#pragma unroll
        for (int i = 0; i < 4; i++) {
            float rowmax = fmaxf(fmaxf(s[i][0], s[i][1]), fmaxf(s[i][2], s[i][3]));
#pragma unroll
            for (int off = 8; off >= 1; off >>= 1)
                rowmax = fmaxf(rowmax, __shfl_xor_sync(0xffffffffu, rowmax, off));
            float newm  = fmaxf(m[i], rowmax);
            float alpha = __expf(m[i] - newm);
            float rsum = 0.f;
#pragma unroll
            for (int j = 0; j < 4; j++) {
                float p = __expf(s[i][j] - newm);
                s[i][j] = p;
                rsum += p;
            }
#pragma unroll
            for (int off = 8; off >= 1; off >>= 1)
                rsum += __shfl_xor_sync(0xffffffffu, rsum, off);
            l[i] = l[i] * alpha + rsum;
            m[i] = newm;
#pragma unroll
            for (int j = 0; j < 8; j++) o[i][j] *= alpha;
        }

#pragma unroll
        for (int i = 0; i < 4; i++)
#pragma unroll
            for (int j = 0; j < 4; j++)
                Ps[(ty * 4 + i) * 65 + tx * 4 + j] = s[i][j];
        __syncthreads();

#pragma unroll 2
        for (int k = 0; k < 64; k++) {
            float p[4];
#pragma unroll
            for (int i = 0; i < 4; i++) p[i] = Ps[(ty * 4 + i) * 65 + k];
            float4 v0 = *(const float4*)(Vs + k * 128 + tx * 8);
            float4 v1 = *(const float4*)(Vs + k * 128 + tx * 8 + 4);
#pragma unroll
            for (int i = 0; i < 4; i++) {
                o[i][0] = fmaf(p[i], v0.x, o[i][0]);
                o[i][1] = fmaf(p[i], v0.y, o[i][1]);
                o[i][2] = fmaf(p[i], v0.z, o[i][2]);
                o[i][3] = fmaf(p[i], v0.w, o[i][3]);
                o[i][4] = fmaf(p[i], v1.x, o[i][4]);
                o[i][5] = fmaf(p[i], v1.y, o[i][5]);
                o[i][6] = fmaf(p[i], v1.z, o[i][6]);
                o[i][7] = fmaf(p[i], v1.w, o[i][7]);
            }
        }
        __syncthreads();
    }

#pragma unroll
    for (int i = 0; i < 4; i++) {
        float inv = 1.f / l[i];
        float* op = O + (size_t)(qb * 64 + ty * 4 + i) * HIDDIM + h * HD + tx * 8;
        float4 c0 = make_float4(o[i][0] * inv, o[i][1] * inv, o[i][2] * inv, o[i][3] * inv);
        float4 c1 = make_float4(o[i][4] * inv, o[i][5] * inv, o[i][6] * inv, o[i][7] * inv);
        *(float4*)(op + 0) = c0;
        *(float4*)(op + 4) = c1;
    }
}

// ---------------- launch ----------------
extern "C" void kernel_launch(void* const* d_in, const int* in_sizes, int n_in,
                              void* d_out, int out_size) {
    const float* H  = (const float*)d_in[0];
    const float* Wq = (const float*)d_in[1];
    const float* Wk = (const float*)d_in[2];
    const float* Wv = (const float*)d_in[3];
    const float* Wo = (const float*)d_in[4];
    float* out = (float*)d_out;

    float *qb, *kb, *vb, *ob;
    cudaGetSymbolAddress((void**)&qb, g_Q);
    cudaGetSymbolAddress((void**)&kb, g_K);
    cudaGetSymbolAddress((void**)&vb, g_V);
    cudaGetSymbolAddress((void**)&ob, g_O);

    // QKV projections (tf32 mma.sync tensor cores)
    gemm_mma<<<dim3(HIDDIM / 128, S_LEN / 128), 256>>>(H, Wq, qb, S_LEN, HIDDIM, HIDDIM);
    gemm_mma<<<dim3((NKV * HD) / 128, S_LEN / 128), 256>>>(H, Wk, kb, S_LEN, NKV * HD, HIDDIM);
    gemm_mma<<<dim3((NKV * HD) / 128, S_LEN / 128), 256>>>(H, Wv, vb, S_LEN, NKV * HD, HIDDIM);

    // RoPE on Q and K
    rope_kernel<<<(S_LEN * (NH + NKV) * 64) / 256, 256>>>(qb, kb);

    // attention (fp32 SIMT)
    const int fa_smem = FA_SMEM_FLOATS * (int)sizeof(float);
    cudaFuncSetAttribute(flash_attn, cudaFuncAttributeMaxDynamicSharedMemorySize, fa_smem);
    flash_attn<<<dim3(S_LEN / 64, NH), 256, fa_smem>>>(qb, kb, vb, ob);

    // output projection -> d_out (tf32 mma.sync tensor cores)
    gemm_mma<<<dim3(HIDDIM / 128, S_LEN / 128), 256>>>(ob, Wo, out, S_LEN, HIDDIM, HIDDIM);
}

// round 4
// speedup vs baseline: 3.2223x; 1.6335x over previous
#include <cuda_runtime.h>
#include <math.h>
#include <cstdint>

#define S_LEN  2048
#define HIDDIM 4096
#define NH     32
#define NKV    8
#define HD     128
#define GROUPS 4

// ---------------- scratch (allocation-free) ----------------
__device__ float g_Q[(size_t)S_LEN * HIDDIM];        // 32 MB
__device__ float g_K[(size_t)S_LEN * NKV * HD];      // 8 MB
__device__ float g_V[(size_t)S_LEN * NKV * HD];      // 8 MB
__device__ float g_O[(size_t)S_LEN * HIDDIM];        // 32 MB

// ---------------- common helpers ----------------
__device__ __forceinline__ uint32_t f2tf(float x) {
    uint32_t y;
    asm("cvt.rna.tf32.f32 %0, %1;" : "=r"(y) : "f"(x));
    return y;
}
__device__ __forceinline__ uint32_t smem_u32(const void* p) {
    uint32_t a;
    asm("{ .reg .u64 t; cvta.to.shared.u64 t, %1; cvt.u32.u64 %0, t; }" : "=r"(a) : "l"(p));
    return a;
}
__device__ __forceinline__ void mma16n8k8(float c[4], const uint32_t a[4],
                                          const uint32_t b[2]) {
    asm volatile(
        "mma.sync.aligned.m16n8k8.row.col.f32.tf32.tf32.f32 "
        "{%0,%1,%2,%3}, {%4,%5,%6,%7}, {%8,%9}, {%0,%1,%2,%3};"
        : "+f"(c[0]), "+f"(c[1]), "+f"(c[2]), "+f"(c[3])
        : "r"(a[0]), "r"(a[1]), "r"(a[2]), "r"(a[3]), "r"(b[0]), "r"(b[1]));
}
__device__ __forceinline__ void cp16(uint32_t dst, const void* src) {
    asm volatile("cp.async.cg.shared.global [%0], [%1], 16;" :: "r"(dst), "l"(src));
}

// ================= tf32 mma.sync GEMM with cp.async pipeline =================
// C[M,N] = A[M,K] @ B[N,K]^T. CTA 128x128, 8 warps (64x32 warp tile), BK=16,
// 3 smem stages via cp.async, fp32 staged, tf32 cvt register-side.

#define BK    16
#define LDA   20
#define GSTG  3
#define STG_F (128 * LDA)
#define GEMM_SMEM (2 * GSTG * STG_F * (int)sizeof(float))

__global__ __launch_bounds__(256, 2)
void gemm_mma(const float* __restrict__ A, const float* __restrict__ B,
              float* __restrict__ C, int M, int N, int K) {
    extern __shared__ float dsm[];
    float* As = dsm;
    float* Bs = dsm + GSTG * STG_F;

    const int tid    = threadIdx.x;
    const int wid    = tid >> 5;
    const int lane   = tid & 31;
    const int grp    = lane >> 2;
    const int thr4   = lane & 3;
    const int warp_m = (wid & 1) * 64;
    const int warp_n = (wid >> 1) * 32;
    const int bm     = blockIdx.y * 128;
    const int bn     = blockIdx.x * 128;
    const int nk     = K / BK;

    // loader: 256 threads, each 2 float4 for A and 2 for B per stage
    const int lr = tid >> 2;          // 0..63
    const int lq = tid & 3;
    const float* gA0 = A + (size_t)(bm + lr) * K + lq * 4;
    const float* gA1 = gA0 + (size_t)64 * K;
    const float* gB0 = B + (size_t)(bn + lr) * K + lq * 4;
    const float* gB1 = gB0 + (size_t)64 * K;
    const uint32_t sA0 = smem_u32(&As[lr * LDA + lq * 4]);
    const uint32_t sA1 = smem_u32(&As[(lr + 64) * LDA + lq * 4]);
    const uint32_t sB0 = smem_u32(&Bs[lr * LDA + lq * 4]);
    const uint32_t sB1 = smem_u32(&Bs[(lr + 64) * LDA + lq * 4]);

    auto issue = [&](int kc, int s) {
        uint32_t off = (uint32_t)(s * STG_F * 4);
        cp16(sA0 + off, gA0 + (size_t)kc * BK);
        cp16(sA1 + off, gA1 + (size_t)kc * BK);
        cp16(sB0 + off, gB0 + (size_t)kc * BK);
        cp16(sB1 + off, gB1 + (size_t)kc * BK);
    };

    float acc[4][4][4];
#pragma unroll
    for (int mt = 0; mt < 4; mt++)
#pragma unroll
        for (int nt = 0; nt < 4; nt++)
#pragma unroll
            for (int i = 0; i < 4; i++) acc[mt][nt][i] = 0.f;

    issue(0, 0);
    asm volatile("cp.async.commit_group;");
    issue(1, 1);
    asm volatile("cp.async.commit_group;");

    for (int kc = 0; kc < nk; kc++) {
        asm volatile("cp.async.wait_group 1;" ::: "memory");
        __syncthreads();
        if (kc + 2 < nk) issue(kc + 2, (kc + 2) % GSTG);
        asm volatile("cp.async.commit_group;");

        const float* sA = As + (kc % GSTG) * STG_F;
        const float* sB = Bs + (kc % GSTG) * STG_F;
#pragma unroll
        for (int k8 = 0; k8 < 2; k8++) {
            uint32_t af[4][4];
#pragma unroll
            for (int mt = 0; mt < 4; mt++) {
                int row = warp_m + mt * 16 + grp;
                int col = k8 * 8 + thr4;
                af[mt][0] = f2tf(sA[row * LDA + col]);
                af[mt][1] = f2tf(sA[(row + 8) * LDA + col]);
                af[mt][2] = f2tf(sA[row * LDA + col + 4]);
                af[mt][3] = f2tf(sA[(row + 8) * LDA + col + 4]);
            }
            uint32_t bf[4][2];
#pragma unroll
            for (int nt = 0; nt < 4; nt++) {
                int n = warp_n + nt * 8 + grp;
                int kcol = k8 * 8 + thr4;
                bf[nt][0] = f2tf(sB[n * LDA + kcol]);
                bf[nt][1] = f2tf(sB[n * LDA + kcol + 4]);
            }
#pragma unroll
            for (int mt = 0; mt < 4; mt++)
#pragma unroll
                for (int nt = 0; nt < 4; nt++)
                    mma16n8k8(acc[mt][nt], af[mt], bf[nt]);
        }
    }

    // epilogue
#pragma unroll
    for (int mt = 0; mt < 4; mt++) {
        int row = bm + warp_m + mt * 16 + grp;
#pragma unroll
        for (int nt = 0; nt < 4; nt++) {
            int col = bn + warp_n + nt * 8 + thr4 * 2;
            *(float2*)(C + (size_t)row * N + col) =
                make_float2(acc[mt][nt][0], acc[mt][nt][1]);
            *(float2*)(C + (size_t)(row + 8) * N + col) =
                make_float2(acc[mt][nt][2], acc[mt][nt][3]);
        }
    }
}

// ---------------- RoPE (in-place on Q and K) ----------------
__global__ void rope_kernel(float* __restrict__ Q, float* __restrict__ K) {
    int idx = blockIdx.x * blockDim.x + threadIdx.x;
    const int total = S_LEN * (NH + NKV) * 64;
    if (idx >= total) return;
    int d   = idx & 63;
    int t   = idx >> 6;
    int h   = t % (NH + NKV);
    int pos = t / (NH + NKV);

    float invf = exp2f((float)d * -0.20762050593046014f);
    float ang  = (float)pos * invf;
    float sv, cv;
    sincosf(ang, &sv, &cv);

    float* base = (h < NH) ? (Q + (size_t)pos * HIDDIM + h * HD)
                           : (K + (size_t)pos * (NKV * HD) + (h - NH) * HD);
    float x1 = base[d];
    float x2 = base[d + 64];
    base[d]      = x1 * cv - x2 * sv;
    base[d + 64] = x2 * cv + x1 * sv;
}

// ---------------- Flash attention on tensor cores (tf32 mma.sync) ----------------
// CTA = (64 q rows, head). 4 warps, warp owns 16 q rows. K tile = 64 keys.
// Ks stride 132 (S-phase conflict-free), Vs stride 136 (PV-phase conflict-free).

#define FA_LDK 132
#define FA_LDV 136
#define FA_SMEM ((64 * FA_LDK + 64 * FA_LDV) * (int)sizeof(float))

__global__ __launch_bounds__(128, 2)
void flash_attn_mma(const float* __restrict__ Q, const float* __restrict__ K,
                    const float* __restrict__ V, float* __restrict__ O) {
    extern __shared__ float smf[];
    float* Ks = smf;                       // [64][FA_LDK] tf32 bits
    float* Vs = smf + 64 * FA_LDK;         // [64][FA_LDV] tf32 bits

    const int qb   = blockIdx.x;
    const int h    = blockIdx.y;
    const int kv   = h / GROUPS;
    const int tid  = threadIdx.x;
    const int w    = tid >> 5;
    const int lane = tid & 31;
    const int grp  = lane >> 2;
    const int thr4 = lane & 3;

    const float scale = 0.08838834764831845f;  // 1/sqrt(128)

    // Q fragments in registers (scale folded in)
    uint32_t qf[16][4];
    const int r0 = qb * 64 + w * 16 + grp;
    const float* Qp0 = Q + (size_t)r0 * HIDDIM + h * HD;
    const float* Qp1 = Qp0 + (size_t)8 * HIDDIM;
#pragma unroll
    for (int kk = 0; kk < 16; kk++) {
        qf[kk][0] = f2tf(Qp0[kk * 8 + thr4] * scale);
        qf[kk][1] = f2tf(Qp1[kk * 8 + thr4] * scale);
        qf[kk][2] = f2tf(Qp0[kk * 8 + thr4 + 4] * scale);
        qf[kk][3] = f2tf(Qp1[kk * 8 + thr4 + 4] * scale);
    }

    float m0 = -1e30f, m1 = -1e30f, l0 = 0.f, l1 = 0.f;
    float o[16][4];
#pragma unroll
    for (int dt = 0; dt < 16; dt++)
#pragma unroll
        for (int i = 0; i < 4; i++) o[dt][i] = 0.f;

    const uint32_t* Ku = (const uint32_t*)Ks;
    const uint32_t* Vu = (const uint32_t*)Vs;

    for (int kt = 0; kt <= qb; kt++) {
        // stage K, V tiles (tf32-converted)
        for (int e = tid; e < 64 * 32; e += 128) {
            int r = e >> 5, c4 = e & 31;
            size_t base = (size_t)(kt * 64 + r) * (NKV * HD) + kv * HD + c4 * 4;
            float4 kq = *(const float4*)(K + base);
            float4 vq = *(const float4*)(V + base);
            *(uint4*)(Ks + r * FA_LDK + c4 * 4) =
                make_uint4(f2tf(kq.x), f2tf(kq.y), f2tf(kq.z), f2tf(kq.w));
            *(uint4*)(Vs + r * FA_LDV + c4 * 4) =
                make_uint4(f2tf(vq.x), f2tf(vq.y), f2tf(vq.z), f2tf(vq.w));
        }
        __syncthreads();

        // ---- S = (Q*scale) @ K^T ----
        float s[8][4];
#pragma unroll
        for (int nt = 0; nt < 8; nt++)
#pragma unroll
            for (int i = 0; i < 4; i++) s[nt][i] = 0.f;

#pragma unroll
        for (int kk = 0; kk < 16; kk++) {
#pragma unroll
            for (int nt = 0; nt < 8; nt++) {
                uint32_t b[2];
                b[0] = Ku[(nt * 8 + grp) * FA_LDK + kk * 8 + thr4];
                b[1] = Ku[(nt * 8 + grp) * FA_LDK + kk * 8 + thr4 + 4];
                mma16n8k8(s[nt], qf[kk], b);
            }
        }

        if (kt == qb) {  // causal mask on diagonal tile
            int rl0 = w * 16 + grp, rl1 = rl0 + 8;
#pragma unroll
            for (int nt = 0; nt < 8; nt++) {
                int c = nt * 8 + thr4 * 2;
                if (c > rl0)     s[nt][0] = -1e30f;
                if (c + 1 > rl0) s[nt][1] = -1e30f;
                if (c > rl1)     s[nt][2] = -1e30f;
                if (c + 1 > rl1) s[nt][3] = -1e30f;
            }
        }

        // ---- online softmax (rows grp / grp+8, reduce over the thr4 quad) ----
        float rm0 = -1e30f, rm1 = -1e30f;
#pragma unroll
        for (int nt = 0; nt < 8; nt++) {
            rm0 = fmaxf(rm0, fmaxf(s[nt][0], s[nt][1]));
            rm1 = fmaxf(rm1, fmaxf(s[nt][2], s[nt][3]));
        }
        rm0 = fmaxf(rm0, __shfl_xor_sync(0xffffffffu, rm0, 1));
        rm0 = fmaxf(rm0, __shfl_xor_sync(0xffffffffu, rm0, 2));
        rm1 = fmaxf(rm1, __shfl_xor_sync(0xffffffffu, rm1, 1));
        rm1 = fmaxf(rm1, __shfl_xor_sync(0xffffffffu, rm1, 2));
        float nm0 = fmaxf(m0, rm0), nm1 = fmaxf(m1, rm1);
        float a0 = __expf(m0 - nm0), a1 = __expf(m1 - nm1);
        float rs0 = 0.f, rs1 = 0.f;
#pragma unroll
        for (int nt = 0; nt < 8; nt++) {
            s[nt][0] = __expf(s[nt][0] - nm0);
            s[nt][1] = __expf(s[nt][1] - nm0);
            s[nt][2] = __expf(s[nt][2] - nm1);
            s[nt][3] = __expf(s[nt][3] - nm1);
            rs0 += s[nt][0] + s[nt][1];
            rs1 += s[nt][2] + s[nt][3];
        }
        rs0 += __shfl_xor_sync(0xffffffffu, rs0, 1);
        rs0 += __shfl_xor_sync(0xffffffffu, rs0, 2);
        rs1 += __shfl_xor_sync(0xffffffffu, rs1, 1);
        rs1 += __shfl_xor_sync(0xffffffffu, rs1, 2);
        l0 = l0 * a0 + rs0;
        l1 = l1 * a1 + rs1;
        m0 = nm0; m1 = nm1;
#pragma unroll
        for (int dt = 0; dt < 16; dt++) {
            o[dt][0] *= a0; o[dt][1] *= a0;
            o[dt][2] *= a1; o[dt][3] *= a1;
        }

        // ---- O += P @ V ----
        const int sl0 = (lane & 28) | (thr4 >> 1);  // source lane for col thr4
        const int sl1 = sl0 + 2;                    // source lane for col thr4+4
        const bool odd = (thr4 & 1);
#pragma unroll
        for (int kk = 0; kk < 8; kk++) {
            // relayout P: C-fragment -> A-fragment via quad shuffles
            float x0 = __shfl_sync(0xffffffffu, s[kk][0], sl0);
            float x1 = __shfl_sync(0xffffffffu, s[kk][1], sl0);
            float x2 = __shfl_sync(0xffffffffu, s[kk][2], sl0);
            float x3 = __shfl_sync(0xffffffffu, s[kk][3], sl0);
            float y0 = __shfl_sync(0xffffffffu, s[kk][0], sl1);
            float y1 = __shfl_sync(0xffffffffu, s[kk][1], sl1);
            float y2 = __shfl_sync(0xffffffffu, s[kk][2], sl1);
            float y3 = __shfl_sync(0xffffffffu, s[kk][3], sl1);
            uint32_t a[4];
            a[0] = f2tf(odd ? x1 : x0);  // P[grp  ][kk*8+thr4]
            a[1] = f2tf(odd ? x3 : x2);  // P[grp+8][kk*8+thr4]
            a[2] = f2tf(odd ? y1 : y0);  // P[grp  ][kk*8+thr4+4]
            a[3] = f2tf(odd ? y3 : y2);  // P[grp+8][kk*8+thr4+4]
#pragma unroll
            for (int dt = 0; dt < 16; dt++) {
                uint32_t b[2];
                b[0] = Vu[(kk * 8 + thr4) * FA_LDV + dt * 8 + grp];
                b[1] = Vu[(kk * 8 + thr4 + 4) * FA_LDV + dt * 8 + grp];
                mma16n8k8(o[dt], a, b);
            }
        }
        __syncthreads();
    }

    // epilogue: normalize, write O[token][h*HD + d]
    float inv0 = 1.f / l0, inv1 = 1.f / l1;
    float* Op0 = O + (size_t)r0 * HIDDIM + h * HD;
    float* Op1 = Op0 + (size_t)8 * HIDDIM;
#pragma unroll
    for (int dt = 0; dt < 16; dt++) {
        int c = dt * 8 + thr4 * 2;
        *(float2*)(Op0 + c) = make_float2(o[dt][0] * inv0, o[dt][1] * inv0);
        *(float2*)(Op1 + c) = make_float2(o[dt][2] * inv1, o[dt][3] * inv1);
    }
}

// ---------------- launch ----------------
extern "C" void kernel_launch(void* const* d_in, const int* in_sizes, int n_in,
                              void* d_out, int out_size) {
    const float* H  = (const float*)d_in[0];
    const float* Wq = (const float*)d_in[1];
    const float* Wk = (const float*)d_in[2];
    const float* Wv = (const float*)d_in[3];
    const float* Wo = (const float*)d_in[4];
    float* out = (float*)d_out;

    float *qb, *kb, *vb, *ob;
    cudaGetSymbolAddress((void**)&qb, g_Q);
    cudaGetSymbolAddress((void**)&kb, g_K);
    cudaGetSymbolAddress((void**)&vb, g_V);
    cudaGetSymbolAddress((void**)&ob, g_O);

    cudaFuncSetAttribute(gemm_mma, cudaFuncAttributeMaxDynamicSharedMemorySize, GEMM_SMEM);
    cudaFuncSetAttribute(flash_attn_mma, cudaFuncAttributeMaxDynamicSharedMemorySize, FA_SMEM);

    // QKV projections
    gemm_mma<<<dim3(HIDDIM / 128, S_LEN / 128), 256, GEMM_SMEM>>>(H, Wq, qb, S_LEN, HIDDIM, HIDDIM);
    gemm_mma<<<dim3((NKV * HD) / 128, S_LEN / 128), 256, GEMM_SMEM>>>(H, Wk, kb, S_LEN, NKV * HD, HIDDIM);
    gemm_mma<<<dim3((NKV * HD) / 128, S_LEN / 128), 256, GEMM_SMEM>>>(H, Wv, vb, S_LEN, NKV * HD, HIDDIM);

    // RoPE
    rope_kernel<<<(S_LEN * (NH + NKV) * 64) / 256, 256>>>(qb, kb);

    // attention (tensor cores)
    flash_attn_mma<<<dim3(S_LEN / 64, NH), 128, FA_SMEM>>>(qb, kb, vb, ob);

    // output projection -> d_out
    gemm_mma<<<dim3(HIDDIM / 128, S_LEN / 128), 256, GEMM_SMEM>>>(ob, Wo, out, S_LEN, HIDDIM, HIDDIM);
}

// round 5
// speedup vs baseline: 3.2230x; 1.0002x over previous
#include <cuda_runtime.h>
#include <math.h>
#include <cstdint>

#define S_LEN  2048
#define HIDDIM 4096
#define NH     32
#define NKV    8
#define HD     128
#define GROUPS 4

// ---------------- scratch (allocation-free) ----------------
__device__ float g_Q[(size_t)S_LEN * HIDDIM];        // 32 MB
__device__ float g_K[(size_t)S_LEN * NKV * HD];      // 8 MB
__device__ float g_V[(size_t)S_LEN * NKV * HD];      // 8 MB
__device__ float g_O[(size_t)S_LEN * HIDDIM];        // 32 MB

// ---------------- common helpers ----------------
__device__ __forceinline__ uint32_t f2tf(float x) {
    uint32_t y;
    asm("cvt.rna.tf32.f32 %0, %1;" : "=r"(y) : "f"(x));
    return y;
}
__device__ __forceinline__ uint32_t smem_u32(const void* p) {
    uint32_t a;
    asm("{ .reg .u64 t; cvta.to.shared.u64 t, %1; cvt.u32.u64 %0, t; }" : "=r"(a) : "l"(p));
    return a;
}
__device__ __forceinline__ void mma16n8k8(float c[4], const uint32_t a[4],
                                          const uint32_t b[2]) {
    asm volatile(
        "mma.sync.aligned.m16n8k8.row.col.f32.tf32.tf32.f32 "
        "{%0,%1,%2,%3}, {%4,%5,%6,%7}, {%8,%9}, {%0,%1,%2,%3};"
        : "+f"(c[0]), "+f"(c[1]), "+f"(c[2]), "+f"(c[3])
        : "r"(a[0]), "r"(a[1]), "r"(a[2]), "r"(a[3]), "r"(b[0]), "r"(b[1]));
}
__device__ __forceinline__ void cp16(uint32_t dst, const void* src) {
    asm volatile("cp.async.cg.shared.global [%0], [%1], 16;" :: "r"(dst), "l"(src));
}

// ================= tf32 mma.sync GEMM with cp.async pipeline =================
// C[M,N] = A[M,K] @ B[N,K]^T. CTA 128x128, 8 warps (64x32 warp tile), BK=16,
// 3 smem stages via cp.async, fp32 staged, tf32 cvt register-side.

#define BK    16
#define LDA   20
#define GSTG  3
#define STG_F (128 * LDA)
#define GEMM_SMEM (2 * GSTG * STG_F * (int)sizeof(float))

__global__ __launch_bounds__(256, 2)
void gemm_mma(const float* __restrict__ A, const float* __restrict__ B,
              float* __restrict__ C, int M, int N, int K) {
    extern __shared__ float dsm[];
    float* As = dsm;
    float* Bs = dsm + GSTG * STG_F;

    const int tid    = threadIdx.x;
    const int wid    = tid >> 5;
    const int lane   = tid & 31;
    const int grp    = lane >> 2;
    const int thr4   = lane & 3;
    const int warp_m = (wid & 1) * 64;
    const int warp_n = (wid >> 1) * 32;
    const int bm     = blockIdx.y * 128;
    const int bn     = blockIdx.x * 128;
    const int nk     = K / BK;

    // loader: 256 threads, each 2 float4 for A and 2 for B per stage
    const int lr = tid >> 2;          // 0..63
    const int lq = tid & 3;
    const float* gA0 = A + (size_t)(bm + lr) * K + lq * 4;
    const float* gA1 = gA0 + (size_t)64 * K;
    const float* gB0 = B + (size_t)(bn + lr) * K + lq * 4;
    const float* gB1 = gB0 + (size_t)64 * K;
    const uint32_t sA0 = smem_u32(&As[lr * LDA + lq * 4]);
    const uint32_t sA1 = smem_u32(&As[(lr + 64) * LDA + lq * 4]);
    const uint32_t sB0 = smem_u32(&Bs[lr * LDA + lq * 4]);
    const uint32_t sB1 = smem_u32(&Bs[(lr + 64) * LDA + lq * 4]);

    auto issue = [&](int kc, int s) {
        uint32_t off = (uint32_t)(s * STG_F * 4);
        cp16(sA0 + off, gA0 + (size_t)kc * BK);
        cp16(sA1 + off, gA1 + (size_t)kc * BK);
        cp16(sB0 + off, gB0 + (size_t)kc * BK);
        cp16(sB1 + off, gB1 + (size_t)kc * BK);
    };

    float acc[4][4][4];
#pragma unroll
    for (int mt = 0; mt < 4; mt++)
#pragma unroll
        for (int nt = 0; nt < 4; nt++)
#pragma unroll
            for (int i = 0; i < 4; i++) acc[mt][nt][i] = 0.f;

    issue(0, 0);
    asm volatile("cp.async.commit_group;");
    issue(1, 1);
    asm volatile("cp.async.commit_group;");

    for (int kc = 0; kc < nk; kc++) {
        asm volatile("cp.async.wait_group 1;" ::: "memory");
        __syncthreads();
        if (kc + 2 < nk) issue(kc + 2, (kc + 2) % GSTG);
        asm volatile("cp.async.commit_group;");

        const float* sA = As + (kc % GSTG) * STG_F;
        const float* sB = Bs + (kc % GSTG) * STG_F;
#pragma unroll
        for (int k8 = 0; k8 < 2; k8++) {
            uint32_t af[4][4];
#pragma unroll
            for (int mt = 0; mt < 4; mt++) {
                int row = warp_m + mt * 16 + grp;
                int col = k8 * 8 + thr4;
                af[mt][0] = f2tf(sA[row * LDA + col]);
                af[mt][1] = f2tf(sA[(row + 8) * LDA + col]);
                af[mt][2] = f2tf(sA[row * LDA + col + 4]);
                af[mt][3] = f2tf(sA[(row + 8) * LDA + col + 4]);
            }
            uint32_t bf[4][2];
#pragma unroll
            for (int nt = 0; nt < 4; nt++) {
                int n = warp_n + nt * 8 + grp;
                int kcol = k8 * 8 + thr4;
                bf[nt][0] = f2tf(sB[n * LDA + kcol]);
                bf[nt][1] = f2tf(sB[n * LDA + kcol + 4]);
            }
#pragma unroll
            for (int mt = 0; mt < 4; mt++)
#pragma unroll
                for (int nt = 0; nt < 4; nt++)
                    mma16n8k8(acc[mt][nt], af[mt], bf[nt]);
        }
    }

    // epilogue
#pragma unroll
    for (int mt = 0; mt < 4; mt++) {
        int row = bm + warp_m + mt * 16 + grp;
#pragma unroll
        for (int nt = 0; nt < 4; nt++) {
            int col = bn + warp_n + nt * 8 + thr4 * 2;
            *(float2*)(C + (size_t)row * N + col) =
                make_float2(acc[mt][nt][0], acc[mt][nt][1]);
            *(float2*)(C + (size_t)(row + 8) * N + col) =
                make_float2(acc[mt][nt][2], acc[mt][nt][3]);
        }
    }
}

// ---------------- RoPE (in-place on Q and K) ----------------
__global__ void rope_kernel(float* __restrict__ Q, float* __restrict__ K) {
    int idx = blockIdx.x * blockDim.x + threadIdx.x;
    const int total = S_LEN * (NH + NKV) * 64;
    if (idx >= total) return;
    int d   = idx & 63;
    int t   = idx >> 6;
    int h   = t % (NH + NKV);
    int pos = t / (NH + NKV);

    float invf = exp2f((float)d * -0.20762050593046014f);
    float ang  = (float)pos * invf;
    float sv, cv;
    sincosf(ang, &sv, &cv);

    float* base = (h < NH) ? (Q + (size_t)pos * HIDDIM + h * HD)
                           : (K + (size_t)pos * (NKV * HD) + (h - NH) * HD);
    float x1 = base[d];
    float x2 = base[d + 64];
    base[d]      = x1 * cv - x2 * sv;
    base[d + 64] = x2 * cv + x1 * sv;
}

// ---------------- Flash attention on tensor cores (tf32 mma.sync) ----------------
// CTA = (64 q rows, head). 4 warps, warp owns 16 q rows. K tile = 64 keys.
// Ks stride 132 (S-phase conflict-free), Vs stride 136 (PV-phase conflict-free).

#define FA_LDK 132
#define FA_LDV 136
#define FA_SMEM ((64 * FA_LDK + 64 * FA_LDV) * (int)sizeof(float))

__global__ __launch_bounds__(128, 2)
void flash_attn_mma(const float* __restrict__ Q, const float* __restrict__ K,
                    const float* __restrict__ V, float* __restrict__ O) {
    extern __shared__ float smf[];
    float* Ks = smf;                       // [64][FA_LDK] tf32 bits
    float* Vs = smf + 64 * FA_LDK;         // [64][FA_LDV] tf32 bits

    const int qb   = blockIdx.x;
    const int h    = blockIdx.y;
    const int kv   = h / GROUPS;
    const int tid  = threadIdx.x;
    const int w    = tid >> 5;
    const int lane = tid & 31;
    const int grp  = lane >> 2;
    const int thr4 = lane & 3;

    const float scale = 0.08838834764831845f;  // 1/sqrt(128)

    // Q fragments in registers (scale folded in)
    uint32_t qf[16][4];
    const int r0 = qb * 64 + w * 16 + grp;
    const float* Qp0 = Q + (size_t)r0 * HIDDIM + h * HD;
    const float* Qp1 = Qp0 + (size_t)8 * HIDDIM;
#pragma unroll
    for (int kk = 0; kk < 16; kk++) {
        qf[kk][0] = f2tf(Qp0[kk * 8 + thr4] * scale);
        qf[kk][1] = f2tf(Qp1[kk * 8 + thr4] * scale);
        qf[kk][2] = f2tf(Qp0[kk * 8 + thr4 + 4] * scale);
        qf[kk][3] = f2tf(Qp1[kk * 8 + thr4 + 4] * scale);
    }

    float m0 = -1e30f, m1 = -1e30f, l0 = 0.f, l1 = 0.f;
    float o[16][4];
#pragma unroll
    for (int dt = 0; dt < 16; dt++)
#pragma unroll
        for (int i = 0; i < 4; i++) o[dt][i] = 0.f;

    const uint32_t* Ku = (const uint32_t*)Ks;
    const uint32_t* Vu = (const uint32_t*)Vs;

    for (int kt = 0; kt <= qb; kt++) {
        // stage K, V tiles (tf32-converted)
        for (int e = tid; e < 64 * 32; e += 128) {
            int r = e >> 5, c4 = e & 31;
            size_t base = (size_t)(kt * 64 + r) * (NKV * HD) + kv * HD + c4 * 4;
            float4 kq = *(const float4*)(K + base);
            float4 vq = *(const float4*)(V + base);
            *(uint4*)(Ks + r * FA_LDK + c4 * 4) =
                make_uint4(f2tf(kq.x), f2tf(kq.y), f2tf(kq.z), f2tf(kq.w));
            *(uint4*)(Vs + r * FA_LDV + c4 * 4) =
                make_uint4(f2tf(vq.x), f2tf(vq.y), f2tf(vq.z), f2tf(vq.w));
        }
        __syncthreads();

        // ---- S = (Q*scale) @ K^T ----
        float s[8][4];
#pragma unroll
        for (int nt = 0; nt < 8; nt++)
#pragma unroll
            for (int i = 0; i < 4; i++) s[nt][i] = 0.f;

#pragma unroll
        for (int kk = 0; kk < 16; kk++) {
#pragma unroll
            for (int nt = 0; nt < 8; nt++) {
                uint32_t b[2];
                b[0] = Ku[(nt * 8 + grp) * FA_LDK + kk * 8 + thr4];
                b[1] = Ku[(nt * 8 + grp) * FA_LDK + kk * 8 + thr4 + 4];
                mma16n8k8(s[nt], qf[kk], b);
            }
        }

        if (kt == qb) {  // causal mask on diagonal tile
            int rl0 = w * 16 + grp, rl1 = rl0 + 8;
#pragma unroll
            for (int nt = 0; nt < 8; nt++) {
                int c = nt * 8 + thr4 * 2;
                if (c > rl0)     s[nt][0] = -1e30f;
                if (c + 1 > rl0) s[nt][1] = -1e30f;
                if (c > rl1)     s[nt][2] = -1e30f;
                if (c + 1 > rl1) s[nt][3] = -1e30f;
            }
        }

        // ---- online softmax (rows grp / grp+8, reduce over the thr4 quad) ----
        float rm0 = -1e30f, rm1 = -1e30f;
#pragma unroll
        for (int nt = 0; nt < 8; nt++) {
            rm0 = fmaxf(rm0, fmaxf(s[nt][0], s[nt][1]));
            rm1 = fmaxf(rm1, fmaxf(s[nt][2], s[nt][3]));
        }
        rm0 = fmaxf(rm0, __shfl_xor_sync(0xffffffffu, rm0, 1));
        rm0 = fmaxf(rm0, __shfl_xor_sync(0xffffffffu, rm0, 2));
        rm1 = fmaxf(rm1, __shfl_xor_sync(0xffffffffu, rm1, 1));
        rm1 = fmaxf(rm1, __shfl_xor_sync(0xffffffffu, rm1, 2));
        float nm0 = fmaxf(m0, rm0), nm1 = fmaxf(m1, rm1);
        float a0 = __expf(m0 - nm0), a1 = __expf(m1 - nm1);
        float rs0 = 0.f, rs1 = 0.f;
#pragma unroll
        for (int nt = 0; nt < 8; nt++) {
            s[nt][0] = __expf(s[nt][0] - nm0);
            s[nt][1] = __expf(s[nt][1] - nm0);
            s[nt][2] = __expf(s[nt][2] - nm1);
            s[nt][3] = __expf(s[nt][3] - nm1);
            rs0 += s[nt][0] + s[nt][1];
            rs1 += s[nt][2] + s[nt][3];
        }
        rs0 += __shfl_xor_sync(0xffffffffu, rs0, 1);
        rs0 += __shfl_xor_sync(0xffffffffu, rs0, 2);
        rs1 += __shfl_xor_sync(0xffffffffu, rs1, 1);
        rs1 += __shfl_xor_sync(0xffffffffu, rs1, 2);
        l0 = l0 * a0 + rs0;
        l1 = l1 * a1 + rs1;
        m0 = nm0; m1 = nm1;
#pragma unroll
        for (int dt = 0; dt < 16; dt++) {
            o[dt][0] *= a0; o[dt][1] *= a0;
            o[dt][2] *= a1; o[dt][3] *= a1;
        }

        // ---- O += P @ V ----
        const int sl0 = (lane & 28) | (thr4 >> 1);  // source lane for col thr4
        const int sl1 = sl0 + 2;                    // source lane for col thr4+4
        const bool odd = (thr4 & 1);
#pragma unroll
        for (int kk = 0; kk < 8; kk++) {
            // relayout P: C-fragment -> A-fragment via quad shuffles
            float x0 = __shfl_sync(0xffffffffu, s[kk][0], sl0);
            float x1 = __shfl_sync(0xffffffffu, s[kk][1], sl0);
            float x2 = __shfl_sync(0xffffffffu, s[kk][2], sl0);
            float x3 = __shfl_sync(0xffffffffu, s[kk][3], sl0);
            float y0 = __shfl_sync(0xffffffffu, s[kk][0], sl1);
            float y1 = __shfl_sync(0xffffffffu, s[kk][1], sl1);
            float y2 = __shfl_sync(0xffffffffu, s[kk][2], sl1);
            float y3 = __shfl_sync(0xffffffffu, s[kk][3], sl1);
            uint32_t a[4];
            a[0] = f2tf(odd ? x1 : x0);  // P[grp  ][kk*8+thr4]
            a[1] = f2tf(odd ? x3 : x2);  // P[grp+8][kk*8+thr4]
            a[2] = f2tf(odd ? y1 : y0);  // P[grp  ][kk*8+thr4+4]
            a[3] = f2tf(odd ? y3 : y2);  // P[grp+8][kk*8+thr4+4]
#pragma unroll
            for (int dt = 0; dt < 16; dt++) {
                uint32_t b[2];
                b[0] = Vu[(kk * 8 + thr4) * FA_LDV + dt * 8 + grp];
                b[1] = Vu[(kk * 8 + thr4 + 4) * FA_LDV + dt * 8 + grp];
                mma16n8k8(o[dt], a, b);
            }
        }
        __syncthreads();
    }

    // epilogue: normalize, write O[token][h*HD + d]
    float inv0 = 1.f / l0, inv1 = 1.f / l1;
    float* Op0 = O + (size_t)r0 * HIDDIM + h * HD;
    float* Op1 = Op0 + (size_t)8 * HIDDIM;
#pragma unroll
    for (int dt = 0; dt < 16; dt++) {
        int c = dt * 8 + thr4 * 2;
        *(float2*)(Op0 + c) = make_float2(o[dt][0] * inv0, o[dt][1] * inv0);
        *(float2*)(Op1 + c) = make_float2(o[dt][2] * inv1, o[dt][3] * inv1);
    }
}

// ---------------- launch ----------------
extern "C" void kernel_launch(void* const* d_in, const int* in_sizes, int n_in,
                              void* d_out, int out_size) {
    const float* H  = (const float*)d_in[0];
    const float* Wq = (const float*)d_in[1];
    const float* Wk = (const float*)d_in[2];
    const float* Wv = (const float*)d_in[3];
    const float* Wo = (const float*)d_in[4];
    float* out = (float*)d_out;

    float *qb, *kb, *vb, *ob;
    cudaGetSymbolAddress((void**)&qb, g_Q);
    cudaGetSymbolAddress((void**)&kb, g_K);
    cudaGetSymbolAddress((void**)&vb, g_V);
    cudaGetSymbolAddress((void**)&ob, g_O);

    cudaFuncSetAttribute(gemm_mma, cudaFuncAttributeMaxDynamicSharedMemorySize, GEMM_SMEM);
    cudaFuncSetAttribute(flash_attn_mma, cudaFuncAttributeMaxDynamicSharedMemorySize, FA_SMEM);

    // QKV projections
    gemm_mma<<<dim3(HIDDIM / 128, S_LEN / 128), 256, GEMM_SMEM>>>(H, Wq, qb, S_LEN, HIDDIM, HIDDIM);
    gemm_mma<<<dim3((NKV * HD) / 128, S_LEN / 128), 256, GEMM_SMEM>>>(H, Wk, kb, S_LEN, NKV * HD, HIDDIM);
    gemm_mma<<<dim3((NKV * HD) / 128, S_LEN / 128), 256, GEMM_SMEM>>>(H, Wv, vb, S_LEN, NKV * HD, HIDDIM);

    // RoPE
    rope_kernel<<<(S_LEN * (NH + NKV) * 64) / 256, 256>>>(qb, kb);

    // attention (tensor cores)
    flash_attn_mma<<<dim3(S_LEN / 64, NH), 128, FA_SMEM>>>(qb, kb, vb, ob);

    // output projection -> d_out
    gemm_mma<<<dim3(HIDDIM / 128, S_LEN / 128), 256, GEMM_SMEM>>>(ob, Wo, out, S_LEN, HIDDIM, HIDDIM);
}